// round 6
// baseline (speedup 1.0000x reference)
#include <cuda_runtime.h>
#include <cstdint>

// Instant-NGP hash-grid encoding, 16 levels, 2 features/level. (resubmit R5 — infra retry #3)
// positions: [N,3] f32 in [0,1);  table: [11445040] f32 (5722520 float2 entries);
// out: [N,32] f32.
//
// Levels 0..5 dense (size = res^3 padded to mult of 8), 6..15 hashed (2^19 mask).
// Dense-level modulo: corner coords can reach `res` when scale==res-1, so the
// raw index can exceed size at levels 0,2,3,4 (but always < 2*size) -> single
// conditional subtract via unsigned min. Levels 1 and 5 provably never wrap.

#define THREADS 256

// ---- packed f32x2 helpers (sm_100+) ----
__device__ __forceinline__ uint64_t mul2(uint64_t a, uint64_t b) {
    uint64_t r; asm("mul.rn.f32x2 %0, %1, %2;" : "=l"(r) : "l"(a), "l"(b)); return r;
}
__device__ __forceinline__ uint64_t fma2(uint64_t a, uint64_t b, uint64_t c) {
    uint64_t r; asm("fma.rn.f32x2 %0, %1, %2, %3;" : "=l"(r) : "l"(a), "l"(b), "l"(c)); return r;
}
__device__ __forceinline__ uint64_t pack2(float x) {
    uint64_t r; asm("mov.b64 %0, {%1, %1};" : "=l"(r) : "f"(x)); return r;
}
// lerp(a,b,t) = (1-t)*a + t*b on packed float2
__device__ __forceinline__ uint64_t lerp2p(uint64_t a, uint64_t b, uint64_t t2, uint64_t omt2) {
    return fma2(t2, b, mul2(omt2, a));
}

__global__ __launch_bounds__(THREADS)
void hash_encode_kernel(const float* __restrict__ pos,
                        const float* __restrict__ table,
                        float* __restrict__ out,
                        int n)
{
    const int i = blockIdx.x * THREADS + threadIdx.x;
    if (i >= n) return;

    // scale_l replicating the reference's float32 pipeline:
    //   logb_f32 = float32(log(1.3195079565048218)),  scale_l = 16*exp_f32(l*logb_f32) - 1
    const float SCALE[16] = {
        15.0f,
        20.1121272169f,
        26.8576197265f,
        35.7583507266f,
        47.5029360517f,
        63.0000097696f,
        83.4485217584f,
        110.4304959160f,
        146.0334253520f,
        193.0117738230f,
        255.0000781570f,
        336.7941385900f,
        444.7220517000f,
        587.1337911820f,
        775.0472137460f,
        1023.0004689400f
    };
    const uint32_t RES[6]  = {16u, 22u, 28u, 37u, 49u, 65u};
    const uint32_t SIZE[6] = {4096u, 10648u, 21952u, 50656u, 117656u, 274632u};
    // Levels whose max raw index can reach/exceed size (needs one cond-subtract):
    const bool NEEDS_MOD[6] = {true, false, true, true, true, false};
    const uint32_t OFF[16] = {
        0u, 4096u, 14744u, 36696u, 87352u, 205008u,
        479640u, 1003928u, 1528216u, 2052504u, 2576792u,
        3101080u, 3625368u, 4149656u, 4673944u, 5198232u
    };

    const float px = pos[3 * i + 0];
    const float py = pos[3 * i + 1];
    const float pz = pos[3 * i + 2];

    const unsigned long long* __restrict__ tb64 = (const unsigned long long*)table;
    ulonglong2* __restrict__ o2 = (ulonglong2*)(out + (size_t)i * 32);

    uint64_t r_even = 0;   // even-level result, paired with odd level for STG.128

    #pragma unroll
    for (int l = 0; l < 16; ++l) {
        const float s = SCALE[l];
        // separate mul+add (no FMA) to mirror XLA's distinct HLO ops
        const float sx = __fadd_rn(__fmul_rn(px, s), 0.5f);
        const float sy = __fadd_rn(__fmul_rn(py, s), 0.5f);
        const float sz = __fadd_rn(__fmul_rn(pz, s), 0.5f);
        const float flx = floorf(sx);
        const float fly = floorf(sy);
        const float flz = floorf(sz);
        const float tx = sx - flx;
        const float ty = sy - fly;
        const float tz = sz - flz;
        const uint32_t gx = (uint32_t)flx;
        const uint32_t gy = (uint32_t)fly;
        const uint32_t gz = (uint32_t)flz;

        const unsigned long long* __restrict__ tb = tb64 + OFF[l];

        uint64_t f0, f1, f2, f3, f4, f5, f6, f7;

        if (l < 6) {
            // Dense: idx = (x + y*res + z*res^2) % size. Raw < 2*size always,
            // so % == conditional subtract == min(u, u - size) in uint32.
            const uint32_t res  = RES[l];
            const uint32_t res2 = res * res;
            const uint32_t sz_  = SIZE[l];
            const bool     m    = NEEDS_MOD[l];
            const uint32_t x0 = gx,        x1 = gx + 1u;
            const uint32_t y0 = gy * res,  y1 = y0 + res;
            const uint32_t z0 = gz * res2, z1 = z0 + res2;
            const uint32_t yz0 = y0 + z0;
            const uint32_t yz1 = y1 + z0;
            const uint32_t yz2 = y0 + z1;
            const uint32_t yz3 = y1 + z1;
            uint32_t u;
            u = x0 + yz0; f0 = __ldg(tb + (m ? min(u, u - sz_) : u));
            u = x1 + yz0; f1 = __ldg(tb + (m ? min(u, u - sz_) : u));
            u = x0 + yz1; f2 = __ldg(tb + (m ? min(u, u - sz_) : u));
            u = x1 + yz1; f3 = __ldg(tb + (m ? min(u, u - sz_) : u));
            u = x0 + yz2; f4 = __ldg(tb + (m ? min(u, u - sz_) : u));
            u = x1 + yz2; f5 = __ldg(tb + (m ? min(u, u - sz_) : u));
            u = x0 + yz3; f6 = __ldg(tb + (m ? min(u, u - sz_) : u));
            u = x1 + yz3; f7 = __ldg(tb + (m ? min(u, u - sz_) : u));
        } else {
            // Hashed: (x ^ y*P2 ^ z*P3) & (2^19-1); xor+and folds to one LOP3
            const uint32_t P2 = 2654435761u;
            const uint32_t P3 = 805459861u;
            const uint32_t MASK = 524287u;
            const uint32_t x0 = gx,      x1 = gx + 1u;
            const uint32_t y0 = gy * P2, y1 = y0 + P2;
            const uint32_t z0 = gz * P3, z1 = z0 + P3;
            const uint32_t yz0 = y0 ^ z0;
            const uint32_t yz1 = y1 ^ z0;
            const uint32_t yz2 = y0 ^ z1;
            const uint32_t yz3 = y1 ^ z1;
            f0 = __ldg(tb + ((x0 ^ yz0) & MASK));
            f1 = __ldg(tb + ((x1 ^ yz0) & MASK));
            f2 = __ldg(tb + ((x0 ^ yz1) & MASK));
            f3 = __ldg(tb + ((x1 ^ yz1) & MASK));
            f4 = __ldg(tb + ((x0 ^ yz2) & MASK));
            f5 = __ldg(tb + ((x1 ^ yz2) & MASK));
            f6 = __ldg(tb + ((x0 ^ yz3) & MASK));
            f7 = __ldg(tb + ((x1 ^ yz3) & MASK));
        }

        // Trilinear interpolation: 7 packed lerps (f32x2)
        const uint64_t tx2 = pack2(tx), omtx2 = pack2(1.0f - tx);
        const uint64_t ty2 = pack2(ty), omty2 = pack2(1.0f - ty);
        const uint64_t tz2 = pack2(tz), omtz2 = pack2(1.0f - tz);

        uint64_t cx0 = lerp2p(f0, f1, tx2, omtx2);
        uint64_t cx1 = lerp2p(f2, f3, tx2, omtx2);
        uint64_t cx2 = lerp2p(f4, f5, tx2, omtx2);
        uint64_t cx3 = lerp2p(f6, f7, tx2, omtx2);
        uint64_t cy0 = lerp2p(cx0, cx1, ty2, omty2);
        uint64_t cy1 = lerp2p(cx2, cx3, ty2, omty2);
        uint64_t r   = lerp2p(cy0, cy1, tz2, omtz2);

        if (l & 1) {
            ulonglong2 st;
            st.x = r_even;
            st.y = r;
            o2[l >> 1] = st;   // 16B store: halves write-sector amplification
        } else {
            r_even = r;
        }
    }
}

extern "C" void kernel_launch(void* const* d_in, const int* in_sizes, int n_in,
                              void* d_out, int out_size)
{
    // positions: 3*2^20 = 3145728 elements; table: 11445040 elements.
    const float* pos   = (const float*)d_in[0];
    const float* table = (const float*)d_in[1];
    if (n_in >= 2 && in_sizes[0] != 3145728 && in_sizes[1] == 3145728) {
        pos   = (const float*)d_in[1];
        table = (const float*)d_in[0];
    }
    const int n = out_size / 32;
    const int blocks = (n + THREADS - 1) / THREADS;
    hash_encode_kernel<<<blocks, THREADS>>>(pos, table, (float*)d_out, n);
}

// round 8
// speedup vs baseline: 1.0909x; 1.0909x over previous
#include <cuda_runtime.h>
#include <cstdint>

// Instant-NGP hash-grid encoding, 16 levels, 2 features/level.  (R7 resubmit of R6 — infra retry)
// positions: [N,3] f32 in [0,1);  table: [11445040] f32 (5722520 float2 entries); out: [N,32] f32.
//
// L1tex-wavefront-bound (R6 ncu: L1=84.9%, issue=10.5%). Dense levels' x-corner
// pairs (u, u+1) are adjacent 8B entries; repacking them into 16B-aligned pairs
// lets one LDG.128 fetch both corners -> dense gather instructions halve, and the
// shared cache line is charged once instead of twice in the L1 wavefront queue.

#define THREADS 256

// ---- dense pair-table scratch (repacked every launch; deterministic) ----
// Per-level extent covers max base index + res + res^2, +1 for the pair partner:
//   L0:4370  L1:11156  L2:22766  L3:52064  L4:120108  L5:278924
#define TOTAL_D4 489388
__device__ __align__(16) float4 g_dense[TOTAL_D4];   // 7.83 MB

__constant__ uint32_t c_DOFF4[6] = {0u, 4370u, 15526u, 38292u, 90356u, 210464u};

__global__ __launch_bounds__(256)
void repack_dense_kernel(const float* __restrict__ table)
{
    const uint32_t SIZE[6] = {4096u, 10648u, 21952u, 50656u, 117656u, 274632u};
    const uint32_t OFF[6]  = {0u, 4096u, 14744u, 36696u, 87352u, 205008u};
    int t = blockIdx.x * 256 + threadIdx.x;
    if (t >= TOTAL_D4) return;
    int l = 0;
    if (t >= (int)c_DOFF4[1]) l = 1;
    if (t >= (int)c_DOFF4[2]) l = 2;
    if (t >= (int)c_DOFF4[3]) l = 3;
    if (t >= (int)c_DOFF4[4]) l = 4;
    if (t >= (int)c_DOFF4[5]) l = 5;
    const uint32_t u = (uint32_t)t - c_DOFF4[l];
    const uint32_t s = SIZE[l];
    const uint32_t v0 = (u >= s) ? (u - s) : u;       // u < 2s always
    const uint32_t w  = u + 1u;
    const uint32_t v1 = (w >= s) ? (w - s) : w;
    const float2* tb = ((const float2*)table) + OFF[l];
    const float2 a = tb[v0];
    const float2 b = tb[v1];
    g_dense[t] = make_float4(a.x, a.y, b.x, b.y);
}

// ---- packed f32x2 helpers (sm_100+) ----
__device__ __forceinline__ uint64_t mul2(uint64_t a, uint64_t b) {
    uint64_t r; asm("mul.rn.f32x2 %0, %1, %2;" : "=l"(r) : "l"(a), "l"(b)); return r;
}
__device__ __forceinline__ uint64_t fma2(uint64_t a, uint64_t b, uint64_t c) {
    uint64_t r; asm("fma.rn.f32x2 %0, %1, %2, %3;" : "=l"(r) : "l"(a), "l"(b), "l"(c)); return r;
}
__device__ __forceinline__ uint64_t pack2(float x) {
    uint64_t r; asm("mov.b64 %0, {%1, %1};" : "=l"(r) : "f"(x)); return r;
}
__device__ __forceinline__ uint64_t lerp2p(uint64_t a, uint64_t b, uint64_t t2, uint64_t omt2) {
    return fma2(t2, b, mul2(omt2, a));
}

struct Coords { float tx, ty, tz; uint32_t gx, gy, gz; };

__device__ __forceinline__ Coords mk_coords(float px, float py, float pz, float s) {
    Coords c;
    const float sx = __fadd_rn(__fmul_rn(px, s), 0.5f);
    const float sy = __fadd_rn(__fmul_rn(py, s), 0.5f);
    const float sz = __fadd_rn(__fmul_rn(pz, s), 0.5f);
    const float fx = floorf(sx), fy = floorf(sy), fz = floorf(sz);
    c.tx = sx - fx; c.ty = sy - fy; c.tz = sz - fz;
    c.gx = (uint32_t)fx; c.gy = (uint32_t)fy; c.gz = (uint32_t)fz;
    return c;
}

// trilinear from 8 packed-f32x2 corners (x fastest, then y, then z)
__device__ __forceinline__ uint64_t trilerp(uint64_t f0, uint64_t f1, uint64_t f2, uint64_t f3,
                                            uint64_t f4, uint64_t f5, uint64_t f6, uint64_t f7,
                                            float tx, float ty, float tz)
{
    const uint64_t tx2 = pack2(tx), omx = pack2(1.0f - tx);
    const uint64_t ty2 = pack2(ty), omy = pack2(1.0f - ty);
    const uint64_t tz2 = pack2(tz), omz = pack2(1.0f - tz);
    uint64_t cx0 = lerp2p(f0, f1, tx2, omx);
    uint64_t cx1 = lerp2p(f2, f3, tx2, omx);
    uint64_t cx2 = lerp2p(f4, f5, tx2, omx);
    uint64_t cx3 = lerp2p(f6, f7, tx2, omx);
    uint64_t cy0 = lerp2p(cx0, cx1, ty2, omy);
    uint64_t cy1 = lerp2p(cx2, cx3, ty2, omy);
    return lerp2p(cy0, cy1, tz2, omz);
}

__global__ __launch_bounds__(THREADS, 3)
void hash_encode_kernel(const float* __restrict__ pos,
                        const float* __restrict__ table,
                        float* __restrict__ out,
                        int n)
{
    const int i = blockIdx.x * THREADS + threadIdx.x;
    if (i >= n) return;

    // scale_l replicates the reference's float32 log/exp pipeline
    const float SCALE[16] = {
        15.0f,           20.1121272169f,  26.8576197265f,  35.7583507266f,
        47.5029360517f,  63.0000097696f,  83.4485217584f,  110.4304959160f,
        146.0334253520f, 193.0117738230f, 255.0000781570f, 336.7941385900f,
        444.7220517000f, 587.1337911820f, 775.0472137460f, 1023.0004689400f
    };
    const uint32_t RES[6]   = {16u, 22u, 28u, 37u, 49u, 65u};
    const uint32_t DOFF4[6] = {0u, 4370u, 15526u, 38292u, 90356u, 210464u};
    const uint32_t OFF_H[16] = {   // hashed-level offsets (levels 6..15 used)
        0u,0u,0u,0u,0u,0u,
        479640u, 1003928u, 1528216u, 2052504u, 2576792u,
        3101080u, 3625368u, 4149656u, 4673944u, 5198232u
    };

    const float px = pos[3 * i + 0];
    const float py = pos[3 * i + 1];
    const float pz = pos[3 * i + 2];

    const ulonglong2* __restrict__ gd2  = (const ulonglong2*)g_dense;
    const unsigned long long* __restrict__ tb64 = (const unsigned long long*)table;
    ulonglong2* __restrict__ o2 = (ulonglong2*)(out + (size_t)i * 32);

    // ---- dense levels 0..5, two levels in flight per iteration ----
    #pragma unroll
    for (int lp = 0; lp < 3; ++lp) {
        const int lA = 2 * lp, lB = lA + 1;
        const Coords cA = mk_coords(px, py, pz, SCALE[lA]);
        const Coords cB = mk_coords(px, py, pz, SCALE[lB]);

        const uint32_t rA = RES[lA], rA2 = rA * rA;
        const uint32_t bA = cA.gx + cA.gy * rA + cA.gz * rA2;
        const ulonglong2* gA = gd2 + DOFF4[lA];
        ulonglong2 A0 = __ldg(gA + bA);
        ulonglong2 A1 = __ldg(gA + bA + rA);
        ulonglong2 A2 = __ldg(gA + bA + rA2);
        ulonglong2 A3 = __ldg(gA + bA + rA + rA2);

        const uint32_t rB = RES[lB], rB2 = rB * rB;
        const uint32_t bB = cB.gx + cB.gy * rB + cB.gz * rB2;
        const ulonglong2* gB = gd2 + DOFF4[lB];
        ulonglong2 B0 = __ldg(gB + bB);
        ulonglong2 B1 = __ldg(gB + bB + rB);
        ulonglong2 B2 = __ldg(gB + bB + rB2);
        ulonglong2 B3 = __ldg(gB + bB + rB + rB2);

        uint64_t resA = trilerp(A0.x, A0.y, A1.x, A1.y, A2.x, A2.y, A3.x, A3.y,
                                cA.tx, cA.ty, cA.tz);
        uint64_t resB = trilerp(B0.x, B0.y, B1.x, B1.y, B2.x, B2.y, B3.x, B3.y,
                                cB.tx, cB.ty, cB.tz);
        ulonglong2 st; st.x = resA; st.y = resB;
        o2[lp] = st;
    }

    // ---- hashed levels 6..15, two levels in flight per iteration ----
    const uint32_t P2 = 2654435761u;
    const uint32_t P3 = 805459861u;
    const uint32_t MASK = 524287u;

    #pragma unroll
    for (int lp = 3; lp < 8; ++lp) {
        const int lA = 2 * lp, lB = lA + 1;
        const Coords cA = mk_coords(px, py, pz, SCALE[lA]);
        const Coords cB = mk_coords(px, py, pz, SCALE[lB]);

        const unsigned long long* tA = tb64 + OFF_H[lA];
        const uint32_t ax0 = cA.gx,       ax1 = ax0 + 1u;
        const uint32_t ay0 = cA.gy * P2,  ay1 = ay0 + P2;
        const uint32_t az0 = cA.gz * P3,  az1 = az0 + P3;
        const uint32_t ayz0 = ay0 ^ az0, ayz1 = ay1 ^ az0;
        const uint32_t ayz2 = ay0 ^ az1, ayz3 = ay1 ^ az1;
        uint64_t a0 = __ldg(tA + ((ax0 ^ ayz0) & MASK));
        uint64_t a1 = __ldg(tA + ((ax1 ^ ayz0) & MASK));
        uint64_t a2 = __ldg(tA + ((ax0 ^ ayz1) & MASK));
        uint64_t a3 = __ldg(tA + ((ax1 ^ ayz1) & MASK));
        uint64_t a4 = __ldg(tA + ((ax0 ^ ayz2) & MASK));
        uint64_t a5 = __ldg(tA + ((ax1 ^ ayz2) & MASK));
        uint64_t a6 = __ldg(tA + ((ax0 ^ ayz3) & MASK));
        uint64_t a7 = __ldg(tA + ((ax1 ^ ayz3) & MASK));

        const unsigned long long* tB = tb64 + OFF_H[lB];
        const uint32_t bx0 = cB.gx,       bx1 = bx0 + 1u;
        const uint32_t by0 = cB.gy * P2,  by1 = by0 + P2;
        const uint32_t bz0 = cB.gz * P3,  bz1 = bz0 + P3;
        const uint32_t byz0 = by0 ^ bz0, byz1 = by1 ^ bz0;
        const uint32_t byz2 = by0 ^ bz1, byz3 = by1 ^ bz1;
        uint64_t b0 = __ldg(tB + ((bx0 ^ byz0) & MASK));
        uint64_t b1 = __ldg(tB + ((bx1 ^ byz0) & MASK));
        uint64_t b2 = __ldg(tB + ((bx0 ^ byz1) & MASK));
        uint64_t b3 = __ldg(tB + ((bx1 ^ byz1) & MASK));
        uint64_t b4 = __ldg(tB + ((bx0 ^ byz2) & MASK));
        uint64_t b5 = __ldg(tB + ((bx1 ^ byz2) & MASK));
        uint64_t b6 = __ldg(tB + ((bx0 ^ byz3) & MASK));
        uint64_t b7 = __ldg(tB + ((bx1 ^ byz3) & MASK));

        uint64_t resA = trilerp(a0, a1, a2, a3, a4, a5, a6, a7, cA.tx, cA.ty, cA.tz);
        uint64_t resB = trilerp(b0, b1, b2, b3, b4, b5, b6, b7, cB.tx, cB.ty, cB.tz);
        ulonglong2 st; st.x = resA; st.y = resB;
        o2[lp] = st;
    }
}

extern "C" void kernel_launch(void* const* d_in, const int* in_sizes, int n_in,
                              void* d_out, int out_size)
{
    const float* pos   = (const float*)d_in[0];
    const float* table = (const float*)d_in[1];
    if (n_in >= 2 && in_sizes[0] != 3145728 && in_sizes[1] == 3145728) {
        pos   = (const float*)d_in[1];
        table = (const float*)d_in[0];
    }
    const int n = out_size / 32;

    const int rblocks = (TOTAL_D4 + 255) / 256;
    repack_dense_kernel<<<rblocks, 256>>>(table);

    const int blocks = (n + THREADS - 1) / THREADS;
    hash_encode_kernel<<<blocks, THREADS>>>(pos, table, (float*)d_out, n);
}

// round 9
// speedup vs baseline: 1.1186x; 1.0254x over previous
#include <cuda_runtime.h>
#include <cstdint>

// Instant-NGP hash-grid encoding, 16 levels, 2 features/level.
// R8: hashed-level x-pair trick. The hash multiplies x by prime 1, so for even
// gx the two x-corner indices are (idx, idx^1) -> same aligned 16B pair in the
// ORIGINAL table. One LDG.128 fetches both; odd-gx lanes fetch f(x1) with an
// LDG.64 whose even lanes are pointed at a single shared dummy line.

#define THREADS 256

// ---- dense pair-table scratch (repacked every launch; deterministic) ----
#define TOTAL_D4 489388
__device__ __align__(16) float4 g_dense[TOTAL_D4];   // 7.83 MB

__constant__ uint32_t c_DOFF4[6] = {0u, 4370u, 15526u, 38292u, 90356u, 210464u};

__global__ __launch_bounds__(256)
void repack_dense_kernel(const float* __restrict__ table)
{
    const uint32_t SIZE[6] = {4096u, 10648u, 21952u, 50656u, 117656u, 274632u};
    const uint32_t OFF[6]  = {0u, 4096u, 14744u, 36696u, 87352u, 205008u};
    int t = blockIdx.x * 256 + threadIdx.x;
    if (t >= TOTAL_D4) return;
    int l = 0;
    if (t >= (int)c_DOFF4[1]) l = 1;
    if (t >= (int)c_DOFF4[2]) l = 2;
    if (t >= (int)c_DOFF4[3]) l = 3;
    if (t >= (int)c_DOFF4[4]) l = 4;
    if (t >= (int)c_DOFF4[5]) l = 5;
    const uint32_t u = (uint32_t)t - c_DOFF4[l];
    const uint32_t s = SIZE[l];
    const uint32_t v0 = (u >= s) ? (u - s) : u;       // u < 2s always
    const uint32_t w  = u + 1u;
    const uint32_t v1 = (w >= s) ? (w - s) : w;
    const float2* tb = ((const float2*)table) + OFF[l];
    const float2 a = tb[v0];
    const float2 b = tb[v1];
    g_dense[t] = make_float4(a.x, a.y, b.x, b.y);
}

// ---- packed f32x2 helpers (sm_100+) ----
__device__ __forceinline__ uint64_t mul2(uint64_t a, uint64_t b) {
    uint64_t r; asm("mul.rn.f32x2 %0, %1, %2;" : "=l"(r) : "l"(a), "l"(b)); return r;
}
__device__ __forceinline__ uint64_t fma2(uint64_t a, uint64_t b, uint64_t c) {
    uint64_t r; asm("fma.rn.f32x2 %0, %1, %2, %3;" : "=l"(r) : "l"(a), "l"(b), "l"(c)); return r;
}
__device__ __forceinline__ uint64_t pack2(float x) {
    uint64_t r; asm("mov.b64 %0, {%1, %1};" : "=l"(r) : "f"(x)); return r;
}
__device__ __forceinline__ uint64_t lerp2p(uint64_t a, uint64_t b, uint64_t t2, uint64_t omt2) {
    return fma2(t2, b, mul2(omt2, a));
}

struct Coords { float tx, ty, tz; uint32_t gx, gy, gz; };

__device__ __forceinline__ Coords mk_coords(float px, float py, float pz, float s) {
    Coords c;
    const float sx = __fadd_rn(__fmul_rn(px, s), 0.5f);
    const float sy = __fadd_rn(__fmul_rn(py, s), 0.5f);
    const float sz = __fadd_rn(__fmul_rn(pz, s), 0.5f);
    const float fx = floorf(sx), fy = floorf(sy), fz = floorf(sz);
    c.tx = sx - fx; c.ty = sy - fy; c.tz = sz - fz;
    c.gx = (uint32_t)fx; c.gy = (uint32_t)fy; c.gz = (uint32_t)fz;
    return c;
}

// trilinear from 8 packed-f32x2 corners (x fastest, then y, then z)
__device__ __forceinline__ uint64_t trilerp(uint64_t f0, uint64_t f1, uint64_t f2, uint64_t f3,
                                            uint64_t f4, uint64_t f5, uint64_t f6, uint64_t f7,
                                            float tx, float ty, float tz)
{
    const uint64_t tx2 = pack2(tx), omx = pack2(1.0f - tx);
    const uint64_t ty2 = pack2(ty), omy = pack2(1.0f - ty);
    const uint64_t tz2 = pack2(tz), omz = pack2(1.0f - tz);
    uint64_t cx0 = lerp2p(f0, f1, tx2, omx);
    uint64_t cx1 = lerp2p(f2, f3, tx2, omx);
    uint64_t cx2 = lerp2p(f4, f5, tx2, omx);
    uint64_t cx3 = lerp2p(f6, f7, tx2, omx);
    uint64_t cy0 = lerp2p(cx0, cx1, ty2, omy);
    uint64_t cy1 = lerp2p(cx2, cx3, ty2, omy);
    return lerp2p(cy0, cy1, tz2, omz);
}

__global__ __launch_bounds__(THREADS, 3)
void hash_encode_kernel(const float* __restrict__ pos,
                        const float* __restrict__ table,
                        float* __restrict__ out,
                        int n)
{
    const int i = blockIdx.x * THREADS + threadIdx.x;
    if (i >= n) return;

    // scale_l replicates the reference's float32 log/exp pipeline
    const float SCALE[16] = {
        15.0f,           20.1121272169f,  26.8576197265f,  35.7583507266f,
        47.5029360517f,  63.0000097696f,  83.4485217584f,  110.4304959160f,
        146.0334253520f, 193.0117738230f, 255.0000781570f, 336.7941385900f,
        444.7220517000f, 587.1337911820f, 775.0472137460f, 1023.0004689400f
    };
    const uint32_t RES[6]   = {16u, 22u, 28u, 37u, 49u, 65u};
    const uint32_t DOFF4[6] = {0u, 4370u, 15526u, 38292u, 90356u, 210464u};
    const uint32_t OFF_H[16] = {
        0u,0u,0u,0u,0u,0u,
        479640u, 1003928u, 1528216u, 2052504u, 2576792u,
        3101080u, 3625368u, 4149656u, 4673944u, 5198232u
    };

    const float px = pos[3 * i + 0];
    const float py = pos[3 * i + 1];
    const float pz = pos[3 * i + 2];

    const ulonglong2* __restrict__ gd2  = (const ulonglong2*)g_dense;
    const unsigned long long* __restrict__ tb64 = (const unsigned long long*)table;
    ulonglong2* __restrict__ o2 = (ulonglong2*)(out + (size_t)i * 32);

    // ---- dense levels 0..5: repacked x-pair table, two levels in flight ----
    #pragma unroll
    for (int lp = 0; lp < 3; ++lp) {
        const int lA = 2 * lp, lB = lA + 1;
        const Coords cA = mk_coords(px, py, pz, SCALE[lA]);
        const Coords cB = mk_coords(px, py, pz, SCALE[lB]);

        const uint32_t rA = RES[lA], rA2 = rA * rA;
        const uint32_t bA = cA.gx + cA.gy * rA + cA.gz * rA2;
        const ulonglong2* gA = gd2 + DOFF4[lA];
        ulonglong2 A0 = __ldg(gA + bA);
        ulonglong2 A1 = __ldg(gA + bA + rA);
        ulonglong2 A2 = __ldg(gA + bA + rA2);
        ulonglong2 A3 = __ldg(gA + bA + rA + rA2);

        const uint32_t rB = RES[lB], rB2 = rB * rB;
        const uint32_t bB = cB.gx + cB.gy * rB + cB.gz * rB2;
        const ulonglong2* gB = gd2 + DOFF4[lB];
        ulonglong2 B0 = __ldg(gB + bB);
        ulonglong2 B1 = __ldg(gB + bB + rB);
        ulonglong2 B2 = __ldg(gB + bB + rB2);
        ulonglong2 B3 = __ldg(gB + bB + rB + rB2);

        uint64_t resA = trilerp(A0.x, A0.y, A1.x, A1.y, A2.x, A2.y, A3.x, A3.y,
                                cA.tx, cA.ty, cA.tz);
        uint64_t resB = trilerp(B0.x, B0.y, B1.x, B1.y, B2.x, B2.y, B3.x, B3.y,
                                cB.tx, cB.ty, cB.tz);
        ulonglong2 st; st.x = resA; st.y = resB;
        o2[lp] = st;
    }

    // ---- hashed levels 6..15: x-pair via prime1==1 adjacency ----
    const uint32_t P2 = 2654435761u;
    const uint32_t P3 = 805459861u;
    const uint32_t MASK = 524287u;

    uint64_t r_even = 0;

    #pragma unroll
    for (int l = 6; l < 16; ++l) {
        const Coords c = mk_coords(px, py, pz, SCALE[l]);
        const unsigned long long* tb = tb64 + OFF_H[l];
        const ulonglong2* tp = (const ulonglong2*)tb;   // aligned 16B pairs

        const uint32_t x0 = c.gx, x1 = x0 + 1u;
        const uint32_t y0 = c.gy * P2, y1 = y0 + P2;
        const uint32_t z0 = c.gz * P3, z1 = z0 + P3;
        const uint32_t yz0 = y0 ^ z0, yz1 = y1 ^ z0;
        const uint32_t yz2 = y0 ^ z1, yz3 = y1 ^ z1;

        const uint32_t i0 = (x0 ^ yz0) & MASK;
        const uint32_t i1 = (x0 ^ yz1) & MASK;
        const uint32_t i2 = (x0 ^ yz2) & MASK;
        const uint32_t i3 = (x0 ^ yz3) & MASK;

        // pair blocks: contain f(x0) always; f(x1) too when x0 is even
        ulonglong2 b0 = __ldg(tp + (i0 >> 1));
        ulonglong2 b1 = __ldg(tp + (i1 >> 1));
        ulonglong2 b2 = __ldg(tp + (i2 >> 1));
        ulonglong2 b3 = __ldg(tp + (i3 >> 1));

        // odd-gx lanes fetch f(x1); even lanes read a shared dummy line (idx 0)
        const bool odd = (x0 & 1u) != 0u;
        const uint32_t j0 = odd ? ((x1 ^ yz0) & MASK) : 0u;
        const uint32_t j1 = odd ? ((x1 ^ yz1) & MASK) : 0u;
        const uint32_t j2 = odd ? ((x1 ^ yz2) & MASK) : 0u;
        const uint32_t j3 = odd ? ((x1 ^ yz3) & MASK) : 0u;
        uint64_t t0 = __ldg(tb + j0);
        uint64_t t1 = __ldg(tb + j1);
        uint64_t t2 = __ldg(tb + j2);
        uint64_t t3 = __ldg(tb + j3);

        const uint64_t f0 = (i0 & 1) ? b0.y : b0.x;
        const uint64_t f2 = (i1 & 1) ? b1.y : b1.x;
        const uint64_t f4 = (i2 & 1) ? b2.y : b2.x;
        const uint64_t f6 = (i3 & 1) ? b3.y : b3.x;
        const uint64_t f1 = odd ? t0 : ((i0 & 1) ? b0.x : b0.y);
        const uint64_t f3 = odd ? t1 : ((i1 & 1) ? b1.x : b1.y);
        const uint64_t f5 = odd ? t2 : ((i2 & 1) ? b2.x : b2.y);
        const uint64_t f7 = odd ? t3 : ((i3 & 1) ? b3.x : b3.y);

        uint64_t r = trilerp(f0, f1, f2, f3, f4, f5, f6, f7, c.tx, c.ty, c.tz);

        if (l & 1) {
            ulonglong2 st; st.x = r_even; st.y = r;
            o2[l >> 1] = st;
        } else {
            r_even = r;
        }
    }
}

extern "C" void kernel_launch(void* const* d_in, const int* in_sizes, int n_in,
                              void* d_out, int out_size)
{
    const float* pos   = (const float*)d_in[0];
    const float* table = (const float*)d_in[1];
    if (n_in >= 2 && in_sizes[0] != 3145728 && in_sizes[1] == 3145728) {
        pos   = (const float*)d_in[1];
        table = (const float*)d_in[0];
    }
    const int n = out_size / 32;

    const int rblocks = (TOTAL_D4 + 255) / 256;
    repack_dense_kernel<<<rblocks, 256>>>(table);

    const int blocks = (n + THREADS - 1) / THREADS;
    hash_encode_kernel<<<blocks, THREADS>>>(pos, table, (float*)d_out, n);
}